// round 1
// baseline (speedup 1.0000x reference)
#include <cuda_runtime.h>
#include <cuda_bf16.h>

#define D     512
#define LD    2
#define NTR   16384
#define NT    8192
#define NCLS  16

#define TI      128     // test points per CTA (1 per thread)
#define JT      128     // j tile staged in shared
#define NSPLIT  8
#define JCHUNK  (NTR / NSPLIT)   // 2048

// ---------------- device scratch (no allocs allowed) ----------------
__device__ float2 g_q[NT];          // q pre-scaled by log2(e)
__device__ float2 g_k[NTR];
__device__ float4 g_pnum[NSPLIT * NT * 4];   // partial numerators [split][i][16]
__device__ float  g_pden[NSPLIT * NT];       // partial denominators

// ---------------- helpers ----------------
__device__ __forceinline__ float ex2f(float x) {
    float r;
    asm("ex2.approx.ftz.f32 %0, %1;" : "=f"(r) : "f"(x));
    return r;
}

__device__ __forceinline__ void ffma2(unsigned long long& d,
                                      unsigned long long a,
                                      unsigned long long b) {
    asm("fma.rn.f32x2 %0, %1, %2, %0;" : "+l"(d) : "l"(a), "l"(b));
}

__device__ __forceinline__ unsigned long long pack2(float lo, float hi) {
    unsigned long long r;
    asm("mov.b64 %0, {%1, %2};" : "=l"(r) : "f"(lo), "f"(hi));
    return r;
}

// ---------------- kernel 1: projections q = (xt@A)*log2e, k = xtr@A ----------------
__global__ void proj_kernel(const float* __restrict__ xt,
                            const float* __restrict__ xtr,
                            const float* __restrict__ A) {
    int gwarp = (blockIdx.x * blockDim.x + threadIdx.x) >> 5;
    int lane  = threadIdx.x & 31;
    if (gwarp >= NT + NTR) return;

    const float* src;
    float2* dst;
    int row;
    float scale;
    if (gwarp < NT) {
        row = gwarp; src = xt;  dst = g_q; scale = 1.4426950408889634f; // log2(e)
    } else {
        row = gwarp - NT; src = xtr; dst = g_k; scale = 1.0f;
    }

    const float4* xr = reinterpret_cast<const float4*>(src + (size_t)row * D);
    const float2* Av = reinterpret_cast<const float2*>(A);  // A[d] = (A[d][0], A[d][1])

    float s0 = 0.f, s1 = 0.f;
    #pragma unroll
    for (int it = 0; it < 4; it++) {
        int c4 = it * 32 + lane;         // float4 index, 0..127
        float4 x = xr[c4];
        int c = c4 * 4;
        float2 a0 = Av[c + 0];
        float2 a1 = Av[c + 1];
        float2 a2 = Av[c + 2];
        float2 a3 = Av[c + 3];
        s0 += x.x * a0.x + x.y * a1.x + x.z * a2.x + x.w * a3.x;
        s1 += x.x * a0.y + x.y * a1.y + x.z * a2.y + x.w * a3.y;
    }
    #pragma unroll
    for (int off = 16; off > 0; off >>= 1) {
        s0 += __shfl_xor_sync(0xFFFFFFFFu, s0, off);
        s1 += __shfl_xor_sync(0xFFFFFFFFu, s1, off);
    }
    if (lane == 0) dst[row] = make_float2(s0 * scale, s1 * scale);
}

// ---------------- kernel 2: streaming softmax-weighted accumulation ----------------
// CTA = 128 threads, each owns one test point i; blockIdx.x = i-tile, blockIdx.y = j-split.
// No max-subtraction needed: |logit| is small (q,k ~ O(1)), exp range is safe in fp32,
// so partials across splits combine by plain addition.
__global__ __launch_bounds__(TI) void attn_kernel(const float* __restrict__ ytr) {
    __shared__ float2 sk[JT];
    __shared__ float4 sy[JT * 4];     // 16 floats per j row

    int tid   = threadIdx.x;
    int i     = blockIdx.x * TI + tid;
    int split = blockIdx.y;
    int j0    = split * JCHUNK;

    float2 q = g_q[i];

    unsigned long long acc[8];
    #pragma unroll
    for (int u = 0; u < 8; u++) acc[u] = 0ull;
    float den = 0.f;

    const float4* ybase = reinterpret_cast<const float4*>(ytr);

    for (int s = 0; s < JCHUNK; s += JT) {
        __syncthreads();
        sk[tid] = g_k[j0 + s + tid];
        const float4* ysrc = ybase + (size_t)(j0 + s) * 4;
        #pragma unroll
        for (int u = 0; u < 4; u++)
            sy[tid + u * TI] = ysrc[tid + u * TI];
        __syncthreads();

        #pragma unroll 4
        for (int j = 0; j < JT; j++) {
            float2 kj = sk[j];
            float l = q.x * kj.x + q.y * kj.y;     // already in log2 units
            float w = ex2f(l);
            den += w;
            unsigned long long ww = pack2(w, w);
            const ulonglong2* yv = reinterpret_cast<const ulonglong2*>(&sy[j * 4]);
            ulonglong2 v0 = yv[0];
            ulonglong2 v1 = yv[1];
            ulonglong2 v2 = yv[2];
            ulonglong2 v3 = yv[3];
            ffma2(acc[0], v0.x, ww); ffma2(acc[1], v0.y, ww);
            ffma2(acc[2], v1.x, ww); ffma2(acc[3], v1.y, ww);
            ffma2(acc[4], v2.x, ww); ffma2(acc[5], v2.y, ww);
            ffma2(acc[6], v3.x, ww); ffma2(acc[7], v3.y, ww);
        }
    }

    // write partials (4 x STG.128)
    ulonglong2* pn = reinterpret_cast<ulonglong2*>(&g_pnum[((size_t)split * NT + i) * 4]);
    ulonglong2 o0; o0.x = acc[0]; o0.y = acc[1];
    ulonglong2 o1; o1.x = acc[2]; o1.y = acc[3];
    ulonglong2 o2; o2.x = acc[4]; o2.y = acc[5];
    ulonglong2 o3; o3.x = acc[6]; o3.y = acc[7];
    pn[0] = o0; pn[1] = o1; pn[2] = o2; pn[3] = o3;
    g_pden[(size_t)split * NT + i] = den;
}

// ---------------- kernel 3: reduce splits + normalize ----------------
__global__ void reduce_kernel(float* __restrict__ out) {
    int i = blockIdx.x * blockDim.x + threadIdx.x;
    if (i >= NT) return;

    float4 n0 = make_float4(0, 0, 0, 0), n1 = n0, n2 = n0, n3 = n0;
    float d = 0.f;
    #pragma unroll
    for (int s = 0; s < NSPLIT; s++) {
        const float4* p = &g_pnum[((size_t)s * NT + i) * 4];
        float4 a = p[0], b = p[1], c = p[2], e = p[3];
        n0.x += a.x; n0.y += a.y; n0.z += a.z; n0.w += a.w;
        n1.x += b.x; n1.y += b.y; n1.z += b.z; n1.w += b.w;
        n2.x += c.x; n2.y += c.y; n2.z += c.z; n2.w += c.w;
        n3.x += e.x; n3.y += e.y; n3.z += e.z; n3.w += e.w;
        d += g_pden[(size_t)s * NT + i];
    }
    float inv = 1.0f / d;
    float4* o = reinterpret_cast<float4*>(out + (size_t)i * NCLS);
    n0.x *= inv; n0.y *= inv; n0.z *= inv; n0.w *= inv;
    n1.x *= inv; n1.y *= inv; n1.z *= inv; n1.w *= inv;
    n2.x *= inv; n2.y *= inv; n2.z *= inv; n2.w *= inv;
    n3.x *= inv; n3.y *= inv; n3.z *= inv; n3.w *= inv;
    o[0] = n0; o[1] = n1; o[2] = n2; o[3] = n3;
}

// ---------------- launch ----------------
extern "C" void kernel_launch(void* const* d_in, const int* in_sizes, int n_in,
                              void* d_out, int out_size) {
    const float* xtr = (const float*)d_in[0];   // [16384, 512]
    const float* ytr = (const float*)d_in[1];   // [16384, 16]
    const float* xt  = (const float*)d_in[2];   // [8192, 512]
    const float* A   = (const float*)d_in[3];   // [512, 2]
    float* out = (float*)d_out;                 // [8192, 16]

    // 1) projections: one warp per row, (NT+NTR)=24576 warps, 256 thr/CTA
    proj_kernel<<<(NT + NTR) / 8, 256>>>(xt, xtr, A);

    // 2) main streaming kernel: 64 i-tiles x 8 j-splits = 512 CTAs
    dim3 grid(NT / TI, NSPLIT);
    attn_kernel<<<grid, TI>>>(ytr);

    // 3) reduce + normalize
    reduce_kernel<<<NT / 256, 256>>>(out);
}

// round 3
// speedup vs baseline: 5.0931x; 5.0931x over previous
#include <cuda_runtime.h>
#include <cuda_fp16.h>
#include <cstdint>

#define D     512
#define NTR   16384
#define NT    8192
#define NCLS  16

#define NSPLIT  8
#define JCHUNK  (NTR / NSPLIT)       // 2048
#define SCHUNK  256                  // j staged per buffer
#define NSC     (JCHUNK / SCHUNK)    // 8
#define KSTEPS  (SCHUNK / 16)        // 16 mma k-steps per staged chunk
#define MTILE   64                   // i rows per CTA (4 warps x 16)
#define YSTR    24                   // halves per padded ytr row (48B, conflict-free ldmatrix)

#define LOG2E  1.4426950408889634f
#define MS2    (-8.656170245333781f)   // -6 * log2(e), softmax-invariant shift

// ---------------- device scratch ----------------
__device__ float2 g_q[NT];          // q pre-scaled by log2(e)
__device__ float2 g_k[NTR];
__device__ uint4  g_y16[NTR * 2];   // fp16 ytr, 32B per row
__device__ float  g_pnum[NSPLIT * NT * NCLS];
__device__ float  g_pden[NSPLIT * NT];

// ---------------- helpers ----------------
__device__ __forceinline__ float ex2f(float x) {
    float r; asm("ex2.approx.ftz.f32 %0, %1;" : "=f"(r) : "f"(x)); return r;
}
__device__ __forceinline__ uint32_t cvt_f16x2(float hi, float lo) {
    uint32_t r; asm("cvt.rn.f16x2.f32 %0, %1, %2;" : "=r"(r) : "f"(hi), "f"(lo)); return r;
}
__device__ __forceinline__ uint32_t smem_u32(const void* p) {
    uint32_t a;
    asm("{ .reg .u64 t; cvta.to.shared.u64 t, %1; cvt.u32.u64 %0, t; }" : "=r"(a) : "l"(p));
    return a;
}
__device__ __forceinline__ void ldmatrix_x4_trans(uint32_t& r0, uint32_t& r1,
                                                  uint32_t& r2, uint32_t& r3,
                                                  uint32_t addr) {
    asm volatile("ldmatrix.sync.aligned.m8n8.x4.trans.shared.b16 {%0,%1,%2,%3}, [%4];"
                 : "=r"(r0), "=r"(r1), "=r"(r2), "=r"(r3) : "r"(addr));
}
__device__ __forceinline__ void mma16816(float& c0, float& c1, float& c2, float& c3,
                                         uint32_t a0, uint32_t a1, uint32_t a2, uint32_t a3,
                                         uint32_t b0, uint32_t b1) {
    asm volatile("mma.sync.aligned.m16n8k16.row.col.f32.f16.f16.f32 "
                 "{%0,%1,%2,%3}, {%4,%5,%6,%7}, {%8,%9}, {%0,%1,%2,%3};"
                 : "+f"(c0), "+f"(c1), "+f"(c2), "+f"(c3)
                 : "r"(a0), "r"(a1), "r"(a2), "r"(a3), "r"(b0), "r"(b1));
}

// ---------------- kernel 1: projections q=(xt@A)*log2e, k=xtr@A ----------------
__global__ __launch_bounds__(256) void proj_kernel(const float* __restrict__ xt,
                                                   const float* __restrict__ xtr,
                                                   const float* __restrict__ A) {
    __shared__ float sA0[D], sA1[D];
    int tid = threadIdx.x;
    #pragma unroll
    for (int c = tid; c < D; c += 256) {
        float2 a = reinterpret_cast<const float2*>(A)[c];
        sA0[c] = a.x; sA1[c] = a.y;
    }
    __syncthreads();

    int gwarp = blockIdx.x * 8 + (tid >> 5);
    int lane  = tid & 31;

    const float* src;  float2* dst;  int row;  float scale;
    if (gwarp < NT) { row = gwarp;      src = xt;  dst = g_q; scale = LOG2E; }
    else            { row = gwarp - NT; src = xtr; dst = g_k; scale = 1.0f;  }

    const float* xr = src + (size_t)row * D;
    float s0 = 0.f, s1 = 0.f;
    #pragma unroll
    for (int it = 0; it < 16; it++) {
        int c = it * 32 + lane;           // bank = lane: conflict-free LDS
        float x = xr[c];                  // coalesced LDG.32
        s0 = fmaf(x, sA0[c], s0);
        s1 = fmaf(x, sA1[c], s1);
    }
    #pragma unroll
    for (int off = 16; off > 0; off >>= 1) {
        s0 += __shfl_xor_sync(0xFFFFFFFFu, s0, off);
        s1 += __shfl_xor_sync(0xFFFFFFFFu, s1, off);
    }
    if (lane == 0) dst[row] = make_float2(s0 * scale, s1 * scale);
}

// ---------------- kernel 1b: ytr -> fp16 rows (32B each) ----------------
__global__ __launch_bounds__(256) void prep_kernel(const float* __restrict__ ytr) {
    int row = blockIdx.x * 256 + threadIdx.x;
    const float4* src = reinterpret_cast<const float4*>(ytr + (size_t)row * NCLS);
    float4 v0 = src[0], v1 = src[1], v2 = src[2], v3 = src[3];
    uint4 o0, o1;
    o0.x = cvt_f16x2(v0.y, v0.x); o0.y = cvt_f16x2(v0.w, v0.z);
    o0.z = cvt_f16x2(v1.y, v1.x); o0.w = cvt_f16x2(v1.w, v1.z);
    o1.x = cvt_f16x2(v2.y, v2.x); o1.y = cvt_f16x2(v2.w, v2.z);
    o1.z = cvt_f16x2(v3.y, v3.x); o1.w = cvt_f16x2(v3.w, v3.z);
    g_y16[row * 2]     = o0;
    g_y16[row * 2 + 1] = o1;
}

// ---------------- kernel 2: fused exp + mma.sync streaming ----------------
__global__ __launch_bounds__(128, 7) void attn_kernel() {
    __shared__ float2 sk[2][SCHUNK];                         // 2 x 2KB
    __shared__ __align__(16) __half sy[2][SCHUNK * YSTR];    // 2 x 12KB (48B rows)

    int tid  = threadIdx.x;
    int wid  = tid >> 5;
    int lane = tid & 31;
    int g    = lane >> 2;
    int tg   = lane & 3;
    int split = blockIdx.y;
    int r0 = blockIdx.x * MTILE + wid * 16 + g;
    int r1 = r0 + 8;
    int j0 = split * JCHUNK;

    float2 qg = g_q[r0];
    float2 qh = g_q[r1];

    // accumulators: classes n0-7, n8-15, denominator (ones-column MMA)
    float d10 = 0, d11 = 0, d12 = 0, d13 = 0;
    float d20 = 0, d21 = 0, d22 = 0, d23 = 0;
    float e0 = 0, e1 = 0, e2 = 0, e3 = 0;
    const uint32_t ONES = 0x3C003C00u;

    // prefetch registers for staging
    float4 pk;  uint4 py0, py1, py2, py3;

#define LDG_CHUNK(sc) do {                                                   \
        int jb = j0 + (sc) * SCHUNK;                                         \
        pk = reinterpret_cast<const float4*>(g_k)[(jb >> 1) + tid];          \
        int rr = (jb + 2 * tid) * 2;                                         \
        py0 = g_y16[rr]; py1 = g_y16[rr + 1];                                \
        py2 = g_y16[rr + 2]; py3 = g_y16[rr + 3];                            \
    } while (0)

#define STS_CHUNK(b) do {                                                    \
        reinterpret_cast<float4*>(sk[b])[tid] = pk;                          \
        uint4* dr0 = reinterpret_cast<uint4*>(&sy[b][(2 * tid) * YSTR]);     \
        dr0[0] = py0; dr0[1] = py1;                                          \
        uint4* dr1 = reinterpret_cast<uint4*>(&sy[b][(2 * tid + 1) * YSTR]); \
        dr1[0] = py2; dr1[1] = py3;                                          \
    } while (0)

    LDG_CHUNK(0);
    STS_CHUNK(0);
    LDG_CHUNK(1);
    __syncthreads();

    for (int sc = 0; sc < NSC; sc++) {
        int b = sc & 1;
        const float4* k4 = reinterpret_cast<const float4*>(sk[b]);
        uint32_t ybase = smem_u32(&sy[b][(lane & 15) * YSTR]) + (lane >> 4) * 16;

        #pragma unroll 4
        for (int ks = 0; ks < KSTEPS; ks++) {
            // k values: j = ks*16 + {2tg,2tg+1} and +8
            float4 ka = k4[ks * 8 + tg];
            float4 kb = k4[ks * 8 + 4 + tg];

            float wg0 = ex2f(fmaf(qg.x, ka.x, fmaf(qg.y, ka.y, MS2)));
            float wg1 = ex2f(fmaf(qg.x, ka.z, fmaf(qg.y, ka.w, MS2)));
            float wg2 = ex2f(fmaf(qg.x, kb.x, fmaf(qg.y, kb.y, MS2)));
            float wg3 = ex2f(fmaf(qg.x, kb.z, fmaf(qg.y, kb.w, MS2)));
            float wh0 = ex2f(fmaf(qh.x, ka.x, fmaf(qh.y, ka.y, MS2)));
            float wh1 = ex2f(fmaf(qh.x, ka.z, fmaf(qh.y, ka.w, MS2)));
            float wh2 = ex2f(fmaf(qh.x, kb.x, fmaf(qh.y, kb.y, MS2)));
            float wh3 = ex2f(fmaf(qh.x, kb.z, fmaf(qh.y, kb.w, MS2)));

            uint32_t a0 = cvt_f16x2(wg1, wg0);
            uint32_t a1 = cvt_f16x2(wh1, wh0);
            uint32_t a2 = cvt_f16x2(wg3, wg2);
            uint32_t a3 = cvt_f16x2(wh3, wh2);

            uint32_t b0, b1, b2, b3;
            ldmatrix_x4_trans(b0, b1, b2, b3, ybase + (ks * 16) * (YSTR * 2));

            mma16816(d10, d11, d12, d13, a0, a1, a2, a3, b0, b1);   // classes 0-7
            mma16816(d20, d21, d22, d23, a0, a1, a2, a3, b2, b3);   // classes 8-15
            mma16816(e0, e1, e2, e3, a0, a1, a2, a3, ONES, ONES);   // denominator
        }

        if (sc + 1 < NSC) {
            STS_CHUNK(b ^ 1);
            if (sc + 2 < NSC) LDG_CHUNK(sc + 2);
        }
        __syncthreads();
    }

    // write partials
    float* p0 = &g_pnum[((size_t)split * NT + r0) * NCLS];
    float* p1 = &g_pnum[((size_t)split * NT + r1) * NCLS];
    *reinterpret_cast<float2*>(p0 + 2 * tg)     = make_float2(d10, d11);
    *reinterpret_cast<float2*>(p0 + 8 + 2 * tg) = make_float2(d20, d21);
    *reinterpret_cast<float2*>(p1 + 2 * tg)     = make_float2(d12, d13);
    *reinterpret_cast<float2*>(p1 + 8 + 2 * tg) = make_float2(d22, d23);
    if (tg == 0) {
        g_pden[(size_t)split * NT + r0] = e0;
        g_pden[(size_t)split * NT + r1] = e2;
    }
#undef LDG_CHUNK
#undef STS_CHUNK
}

// ---------------- kernel 3: reduce splits + normalize ----------------
__global__ __launch_bounds__(256) void reduce_kernel(float* __restrict__ out) {
    int i = blockIdx.x * blockDim.x + threadIdx.x;
    if (i >= NT) return;

    float4 n0 = make_float4(0, 0, 0, 0), n1 = n0, n2 = n0, n3 = n0;
    float d = 0.f;
    #pragma unroll
    for (int s = 0; s < NSPLIT; s++) {
        const float4* p = reinterpret_cast<const float4*>(&g_pnum[((size_t)s * NT + i) * NCLS]);
        float4 a = p[0], b = p[1], cc = p[2], e = p[3];
        n0.x += a.x;  n0.y += a.y;  n0.z += a.z;  n0.w += a.w;
        n1.x += b.x;  n1.y += b.y;  n1.z += b.z;  n1.w += b.w;
        n2.x += cc.x; n2.y += cc.y; n2.z += cc.z; n2.w += cc.w;
        n3.x += e.x;  n3.y += e.y;  n3.z += e.z;  n3.w += e.w;
        d += g_pden[(size_t)s * NT + i];
    }
    float inv = 1.0f / d;
    float4* o = reinterpret_cast<float4*>(out + (size_t)i * NCLS);
    n0.x *= inv; n0.y *= inv; n0.z *= inv; n0.w *= inv;
    n1.x *= inv; n1.y *= inv; n1.z *= inv; n1.w *= inv;
    n2.x *= inv; n2.y *= inv; n2.z *= inv; n2.w *= inv;
    n3.x *= inv; n3.y *= inv; n3.z *= inv; n3.w *= inv;
    o[0] = n0; o[1] = n1; o[2] = n2; o[3] = n3;
}

// ---------------- launch ----------------
extern "C" void kernel_launch(void* const* d_in, const int* in_sizes, int n_in,
                              void* d_out, int out_size) {
    const float* xtr = (const float*)d_in[0];   // [16384, 512]
    const float* ytr = (const float*)d_in[1];   // [16384, 16]
    const float* xt  = (const float*)d_in[2];   // [8192, 512]
    const float* A   = (const float*)d_in[3];   // [512, 2]
    float* out = (float*)d_out;                 // [8192, 16]

    proj_kernel<<<(NT + NTR) / 8, 256>>>(xt, xtr, A);
    prep_kernel<<<NTR / 256, 256>>>(ytr);

    dim3 grid(NT / MTILE, NSPLIT);               // 128 x 8 = 1024 CTAs
    attn_kernel<<<grid, 128>>>();

    reduce_kernel<<<NT / 256, 256>>>(out);
}

// round 4
// speedup vs baseline: 5.5483x; 1.0894x over previous
#include <cuda_runtime.h>
#include <cuda_fp16.h>
#include <cstdint>

#define D     512
#define NTR   16384
#define NT    8192
#define NCLS  16

#define NSPLIT  8
#define JCHUNK  (NTR / NSPLIT)       // 2048
#define SCHUNK  256                  // j staged per buffer
#define NSC     (JCHUNK / SCHUNK)    // 8
#define KSTEPS  (SCHUNK / 16)        // 16 mma k-steps per staged chunk
#define MTILE   64                   // i rows per CTA (4 warps x 16)
#define YSTR    24                   // halves per padded ytr row (48B, conflict-free ldmatrix)

#define LOG2E  1.4426950408889634f
#define MS2    (-8.656170245333781f)   // -6 * log2(e), softmax-invariant shift

#define PROJ_CTAS ((NT + NTR) / 8)     // 3072
#define PREP_CTAS (NTR / 256)          // 64

// ---------------- device scratch ----------------
__device__ float2 g_q[NT];          // q pre-scaled by log2(e)
__device__ float2 g_k[NTR];
__device__ uint4  g_y16[NTR * 2];   // fp16 ytr, 32B per row
__device__ float  g_pnum[NSPLIT * NT * NCLS];
__device__ float  g_pden[NSPLIT * NT];

// ---------------- helpers ----------------
__device__ __forceinline__ float ex2f(float x) {
    float r; asm("ex2.approx.ftz.f32 %0, %1;" : "=f"(r) : "f"(x)); return r;
}
__device__ __forceinline__ uint32_t cvt_f16x2(float hi, float lo) {
    uint32_t r; asm("cvt.rn.f16x2.f32 %0, %1, %2;" : "=r"(r) : "f"(hi), "f"(lo)); return r;
}
__device__ __forceinline__ uint32_t smem_u32(const void* p) {
    uint32_t a;
    asm("{ .reg .u64 t; cvta.to.shared.u64 t, %1; cvt.u32.u64 %0, t; }" : "=r"(a) : "l"(p));
    return a;
}
__device__ __forceinline__ void ldmatrix_x4_trans(uint32_t& r0, uint32_t& r1,
                                                  uint32_t& r2, uint32_t& r3,
                                                  uint32_t addr) {
    asm volatile("ldmatrix.sync.aligned.m8n8.x4.trans.shared.b16 {%0,%1,%2,%3}, [%4];"
                 : "=r"(r0), "=r"(r1), "=r"(r2), "=r"(r3) : "r"(addr));
}
__device__ __forceinline__ void mma16816(float& c0, float& c1, float& c2, float& c3,
                                         uint32_t a0, uint32_t a1, uint32_t a2, uint32_t a3,
                                         uint32_t b0, uint32_t b1) {
    asm volatile("mma.sync.aligned.m16n8k16.row.col.f32.f16.f16.f32 "
                 "{%0,%1,%2,%3}, {%4,%5,%6,%7}, {%8,%9}, {%0,%1,%2,%3};"
                 : "+f"(c0), "+f"(c1), "+f"(c2), "+f"(c3)
                 : "r"(a0), "r"(a1), "r"(a2), "r"(a3), "r"(b0), "r"(b1));
}

// ---------------- kernel 1: fused projections + ytr->fp16 conversion ----------------
// CTAs [0, PROJ_CTAS): q = (xt@A)*log2e, k = xtr@A   (8 warp-rows per CTA)
// CTAs [PROJ_CTAS, PROJ_CTAS+PREP_CTAS): convert 256 ytr rows to fp16
__global__ __launch_bounds__(256) void proj_prep_kernel(const float* __restrict__ xt,
                                                        const float* __restrict__ xtr,
                                                        const float* __restrict__ A,
                                                        const float* __restrict__ ytr) {
    int tid = threadIdx.x;

    if (blockIdx.x >= PROJ_CTAS) {
        // ---- prep branch ----
        int row = (blockIdx.x - PROJ_CTAS) * 256 + tid;
        const float4* src = reinterpret_cast<const float4*>(ytr + (size_t)row * NCLS);
        float4 v0 = src[0], v1 = src[1], v2 = src[2], v3 = src[3];
        uint4 o0, o1;
        o0.x = cvt_f16x2(v0.y, v0.x); o0.y = cvt_f16x2(v0.w, v0.z);
        o0.z = cvt_f16x2(v1.y, v1.x); o0.w = cvt_f16x2(v1.w, v1.z);
        o1.x = cvt_f16x2(v2.y, v2.x); o1.y = cvt_f16x2(v2.w, v2.z);
        o1.z = cvt_f16x2(v3.y, v3.x); o1.w = cvt_f16x2(v3.w, v3.z);
        g_y16[row * 2]     = o0;
        g_y16[row * 2 + 1] = o1;
        return;
    }

    // ---- proj branch ----
    __shared__ float sA0[D], sA1[D];
    #pragma unroll
    for (int c = tid; c < D; c += 256) {
        float2 a = reinterpret_cast<const float2*>(A)[c];
        sA0[c] = a.x; sA1[c] = a.y;
    }
    __syncthreads();

    int gwarp = blockIdx.x * 8 + (tid >> 5);
    int lane  = tid & 31;

    const float* src;  float2* dst;  int row;  float scale;
    if (gwarp < NT) { row = gwarp;      src = xt;  dst = g_q; scale = LOG2E; }
    else            { row = gwarp - NT; src = xtr; dst = g_k; scale = 1.0f;  }

    const float* xr = src + (size_t)row * D;
    float s0 = 0.f, s1 = 0.f;
    #pragma unroll
    for (int it = 0; it < 16; it++) {
        int c = it * 32 + lane;           // bank = lane: conflict-free LDS
        float x = xr[c];                  // coalesced LDG.32
        s0 = fmaf(x, sA0[c], s0);
        s1 = fmaf(x, sA1[c], s1);
    }
    #pragma unroll
    for (int off = 16; off > 0; off >>= 1) {
        s0 += __shfl_xor_sync(0xFFFFFFFFu, s0, off);
        s1 += __shfl_xor_sync(0xFFFFFFFFu, s1, off);
    }
    if (lane == 0) dst[row] = make_float2(s0 * scale, s1 * scale);
}

// ---------------- kernel 2: fused exp + mma.sync streaming ----------------
__global__ __launch_bounds__(128, 7) void attn_kernel() {
    __shared__ float2 sk[2][SCHUNK];                         // 2 x 2KB
    __shared__ __align__(16) __half sy[2][SCHUNK * YSTR];    // 2 x 12KB (48B rows)

    int tid  = threadIdx.x;
    int wid  = tid >> 5;
    int lane = tid & 31;
    int g    = lane >> 2;
    int tg   = lane & 3;
    int split = blockIdx.y;
    int r0 = blockIdx.x * MTILE + wid * 16 + g;
    int r1 = r0 + 8;
    int j0 = split * JCHUNK;

    float2 qg = g_q[r0];
    float2 qh = g_q[r1];

    // accumulators: classes n0-7, n8-15, denominator (ones-column MMA)
    float d10 = 0, d11 = 0, d12 = 0, d13 = 0;
    float d20 = 0, d21 = 0, d22 = 0, d23 = 0;
    float e0 = 0, e1 = 0, e2 = 0, e3 = 0;
    const uint32_t ONES = 0x3C003C00u;

    // prefetch registers for staging
    float4 pk;  uint4 py0, py1, py2, py3;

#define LDG_CHUNK(sc) do {                                                   \
        int jb = j0 + (sc) * SCHUNK;                                         \
        pk = reinterpret_cast<const float4*>(g_k)[(jb >> 1) + tid];          \
        int rr = (jb + 2 * tid) * 2;                                         \
        py0 = g_y16[rr]; py1 = g_y16[rr + 1];                                \
        py2 = g_y16[rr + 2]; py3 = g_y16[rr + 3];                            \
    } while (0)

#define STS_CHUNK(b) do {                                                    \
        reinterpret_cast<float4*>(sk[b])[tid] = pk;                          \
        uint4* dr0 = reinterpret_cast<uint4*>(&sy[b][(2 * tid) * YSTR]);     \
        dr0[0] = py0; dr0[1] = py1;                                          \
        uint4* dr1 = reinterpret_cast<uint4*>(&sy[b][(2 * tid + 1) * YSTR]); \
        dr1[0] = py2; dr1[1] = py3;                                          \
    } while (0)

    LDG_CHUNK(0);
    STS_CHUNK(0);
    LDG_CHUNK(1);
    __syncthreads();

    for (int sc = 0; sc < NSC; sc++) {
        int b = sc & 1;
        const float4* k4 = reinterpret_cast<const float4*>(sk[b]);
        uint32_t ybase = smem_u32(&sy[b][(lane & 15) * YSTR]) + (lane >> 4) * 16;

        #pragma unroll 4
        for (int ks = 0; ks < KSTEPS; ks++) {
            // k values: j = ks*16 + {2tg,2tg+1} and +8
            float4 ka = k4[ks * 8 + tg];
            float4 kb = k4[ks * 8 + 4 + tg];

            float wg0 = ex2f(fmaf(qg.x, ka.x, fmaf(qg.y, ka.y, MS2)));
            float wg1 = ex2f(fmaf(qg.x, ka.z, fmaf(qg.y, ka.w, MS2)));
            float wg2 = ex2f(fmaf(qg.x, kb.x, fmaf(qg.y, kb.y, MS2)));
            float wg3 = ex2f(fmaf(qg.x, kb.z, fmaf(qg.y, kb.w, MS2)));
            float wh0 = ex2f(fmaf(qh.x, ka.x, fmaf(qh.y, ka.y, MS2)));
            float wh1 = ex2f(fmaf(qh.x, ka.z, fmaf(qh.y, ka.w, MS2)));
            float wh2 = ex2f(fmaf(qh.x, kb.x, fmaf(qh.y, kb.y, MS2)));
            float wh3 = ex2f(fmaf(qh.x, kb.z, fmaf(qh.y, kb.w, MS2)));

            uint32_t a0 = cvt_f16x2(wg1, wg0);
            uint32_t a1 = cvt_f16x2(wh1, wh0);
            uint32_t a2 = cvt_f16x2(wg3, wg2);
            uint32_t a3 = cvt_f16x2(wh3, wh2);

            uint32_t b0, b1, b2, b3;
            ldmatrix_x4_trans(b0, b1, b2, b3, ybase + (ks * 16) * (YSTR * 2));

            mma16816(d10, d11, d12, d13, a0, a1, a2, a3, b0, b1);   // classes 0-7
            mma16816(d20, d21, d22, d23, a0, a1, a2, a3, b2, b3);   // classes 8-15
            mma16816(e0, e1, e2, e3, a0, a1, a2, a3, ONES, ONES);   // denominator
        }

        if (sc + 1 < NSC) {
            STS_CHUNK(b ^ 1);
            if (sc + 2 < NSC) LDG_CHUNK(sc + 2);
        }
        __syncthreads();
    }

    // write partials
    float* p0 = &g_pnum[((size_t)split * NT + r0) * NCLS];
    float* p1 = &g_pnum[((size_t)split * NT + r1) * NCLS];
    *reinterpret_cast<float2*>(p0 + 2 * tg)     = make_float2(d10, d11);
    *reinterpret_cast<float2*>(p0 + 8 + 2 * tg) = make_float2(d20, d21);
    *reinterpret_cast<float2*>(p1 + 2 * tg)     = make_float2(d12, d13);
    *reinterpret_cast<float2*>(p1 + 8 + 2 * tg) = make_float2(d22, d23);
    if (tg == 0) {
        g_pden[(size_t)split * NT + r0] = e0;
        g_pden[(size_t)split * NT + r1] = e2;
    }
#undef LDG_CHUNK
#undef STS_CHUNK
}

// ---------------- kernel 3: reduce splits + normalize (thread per i x class-quad) ----------------
__global__ __launch_bounds__(256) void reduce_kernel(float* __restrict__ out) {
    int idx = blockIdx.x * 256 + threadIdx.x;     // 0 .. NT*4-1
    int i   = idx >> 2;
    int tg  = idx & 3;

    float4 n = make_float4(0, 0, 0, 0);
    float d = 0.f;
    #pragma unroll
    for (int s = 0; s < NSPLIT; s++) {
        float4 a = *reinterpret_cast<const float4*>(
            &g_pnum[((size_t)s * NT + i) * NCLS + tg * 4]);
        n.x += a.x; n.y += a.y; n.z += a.z; n.w += a.w;
        d += g_pden[(size_t)s * NT + i];
    }
    float inv = 1.0f / d;
    n.x *= inv; n.y *= inv; n.z *= inv; n.w *= inv;
    *reinterpret_cast<float4*>(out + (size_t)i * NCLS + tg * 4) = n;
}

// ---------------- launch ----------------
extern "C" void kernel_launch(void* const* d_in, const int* in_sizes, int n_in,
                              void* d_out, int out_size) {
    const float* xtr = (const float*)d_in[0];   // [16384, 512]
    const float* ytr = (const float*)d_in[1];   // [16384, 16]
    const float* xt  = (const float*)d_in[2];   // [8192, 512]
    const float* A   = (const float*)d_in[3];   // [512, 2]
    float* out = (float*)d_out;                 // [8192, 16]

    proj_prep_kernel<<<PROJ_CTAS + PREP_CTAS, 256>>>(xt, xtr, A, ytr);

    dim3 grid(NT / MTILE, NSPLIT);               // 128 x 8 = 1024 CTAs
    attn_kernel<<<grid, 128>>>();

    reduce_kernel<<<NT * 4 / 256, 256>>>(out);   // 128 CTAs
}